// round 1
// baseline (speedup 1.0000x reference)
#include <cuda_runtime.h>
#include <cuda_bf16.h>
#include <math.h>

#define BB 64
#define TT 2048
#define DD 128
#define UU 128
#define TM 64            // tokens per block in scores kernel

// scratch: scores [B*T] (512 KB) — __device__ global per allocation rules
__device__ float g_scores[BB * TT];

// ---------------------------------------------------------------------------
// Kernel 1: fused (W1+W2) GEMM + tanh + V-dot -> scores[b*T + t]
// grid = B*T/TM = 2048 blocks, 256 threads
// dynamic smem: sW[128*128] + sX[128][65]  (~96.5 KB)
// Thread map: warp r (0..7) owns tokens r*8..r*8+7; lane c owns u = 4c..4c+3.
// ---------------------------------------------------------------------------
__global__ void scores_kernel(const float* __restrict__ x,
                              const float* __restrict__ W1,
                              const float* __restrict__ W2,
                              const float* __restrict__ b1,
                              const float* __restrict__ b2,
                              const float* __restrict__ Vw) {
    extern __shared__ float smem[];
    float* sW = smem;                 // [k][u], 128*128
    float* sX = smem + 128 * 128;     // [k][t], padded rows of 65

    const int tid = threadIdx.x;

    // Build Wsum = W1 + W2 directly into smem (float4, conflict-free)
    const float4* W1v = (const float4*)W1;
    const float4* W2v = (const float4*)W2;
    float4* sWv = (float4*)sW;
#pragma unroll 4
    for (int i = tid; i < 128 * 128 / 4; i += 256) {
        float4 a = W1v[i], b = W2v[i];
        float4 cc;
        cc.x = a.x + b.x; cc.y = a.y + b.y; cc.z = a.z + b.z; cc.w = a.w + b.w;
        sWv[i] = cc;
    }

    // Load x tile [TM tokens][128] transposed into sX[k][t] (coalesced float4 gmem reads)
    const size_t base = (size_t)blockIdx.x * TM * DD;
#pragma unroll 2
    for (int i = tid; i < TM * 32; i += 256) {
        int t  = i >> 5;     // token within tile
        int k4 = i & 31;     // float4 index along k
        float4 v = ((const float4*)(x + base + (size_t)t * DD))[k4];
        sX[(k4 * 4 + 0) * 65 + t] = v.x;
        sX[(k4 * 4 + 1) * 65 + t] = v.y;
        sX[(k4 * 4 + 2) * 65 + t] = v.z;
        sX[(k4 * 4 + 3) * 65 + t] = v.w;
    }
    __syncthreads();

    const int r = tid >> 5;   // warp id = token group
    const int c = tid & 31;   // lane id = u group

    float acc[8][4];
#pragma unroll
    for (int i = 0; i < 8; i++)
#pragma unroll
        for (int j = 0; j < 4; j++) acc[i][j] = 0.f;

    const float4* sW4 = (const float4*)sW;

#pragma unroll 8
    for (int k = 0; k < 128; k++) {
        float4 w = sW4[k * 32 + c];            // conflict-free: lane-consecutive float4
        float xv[8];
#pragma unroll
        for (int i = 0; i < 8; i++) xv[i] = sX[k * 65 + r * 8 + i];  // broadcast
#pragma unroll
        for (int i = 0; i < 8; i++) {
            acc[i][0] = fmaf(xv[i], w.x, acc[i][0]);
            acc[i][1] = fmaf(xv[i], w.y, acc[i][1]);
            acc[i][2] = fmaf(xv[i], w.z, acc[i][2]);
            acc[i][3] = fmaf(xv[i], w.w, acc[i][3]);
        }
    }

    // Epilogue: tanh, weight by V, reduce over u (across lanes)
    float bb[4], vv[4];
#pragma unroll
    for (int j = 0; j < 4; j++) {
        int u = c * 4 + j;
        bb[j] = b1[u] + b2[u];
        vv[j] = Vw[u];
    }
#pragma unroll
    for (int i = 0; i < 8; i++) {
        float p = 0.f;
#pragma unroll
        for (int j = 0; j < 4; j++) p += tanhf(acc[i][j] + bb[j]) * vv[j];
#pragma unroll
        for (int off = 16; off > 0; off >>= 1)
            p += __shfl_xor_sync(0xffffffffu, p, off);
        if (c == 0)
            g_scores[(size_t)blockIdx.x * TM + r * 8 + i] = p;
    }
}

// ---------------------------------------------------------------------------
// Kernel 2: per-batch softmax over T + context = sum_t attn[t] * x[b,t,:]
// grid = B blocks, 512 threads. (V_b is softmax-invariant; dropped.)
// ---------------------------------------------------------------------------
__global__ void ctx_kernel(const float* __restrict__ x, float* __restrict__ out) {
    __shared__ float attn[TT];        // 8 KB
    __shared__ float red[16];
    __shared__ float part[4][DD];

    const int b = blockIdx.x;
    const int tid = threadIdx.x;
    const float* sc = g_scores + (size_t)b * TT;

    // --- max over T ---
    float m = -1e30f;
    for (int i = tid; i < TT; i += 512) m = fmaxf(m, sc[i]);
#pragma unroll
    for (int off = 16; off > 0; off >>= 1)
        m = fmaxf(m, __shfl_xor_sync(0xffffffffu, m, off));
    if ((tid & 31) == 0) red[tid >> 5] = m;
    __syncthreads();
    if (tid < 32) {
        float v = (tid < 16) ? red[tid] : -1e30f;
#pragma unroll
        for (int off = 8; off > 0; off >>= 1)
            v = fmaxf(v, __shfl_xor_sync(0xffffffffu, v, off));
        if (tid == 0) red[0] = v;
    }
    __syncthreads();
    m = red[0];
    __syncthreads();

    // --- exp + sum ---
    float s = 0.f;
    for (int i = tid; i < TT; i += 512) {
        float e = expf(sc[i] - m);
        attn[i] = e;
        s += e;
    }
#pragma unroll
    for (int off = 16; off > 0; off >>= 1)
        s += __shfl_xor_sync(0xffffffffu, s, off);
    if ((tid & 31) == 0) red[tid >> 5] = s;
    __syncthreads();
    if (tid < 32) {
        float v = (tid < 16) ? red[tid] : 0.f;
#pragma unroll
        for (int off = 8; off > 0; off >>= 1)
            v += __shfl_xor_sync(0xffffffffu, v, off);
        if (tid == 0) red[0] = v;
    }
    __syncthreads();
    const float inv = 1.f / red[0];

    // --- context: 4 t-parallel groups x 128 d ---
    const int g = tid >> 7;      // 0..3
    const int d = tid & 127;
    const float* xb = x + (size_t)b * TT * DD + d;
    float acc = 0.f;
#pragma unroll 8
    for (int t = g; t < TT; t += 4)
        acc += attn[t] * xb[(size_t)t * DD];
    part[g][d] = acc * inv;
    __syncthreads();
    if (tid < DD)
        out[(size_t)b * DD + tid] =
            part[0][tid] + part[1][tid] + part[2][tid] + part[3][tid];
}

// ---------------------------------------------------------------------------
extern "C" void kernel_launch(void* const* d_in, const int* in_sizes, int n_in,
                              void* d_out, int out_size) {
    const float* enc = (const float*)d_in[0];
    const float* W1w = (const float*)d_in[1];
    const float* W1b = (const float*)d_in[2];
    const float* W2w = (const float*)d_in[3];
    const float* W2b = (const float*)d_in[4];
    const float* Vw  = (const float*)d_in[5];
    // d_in[6] = V_b: softmax-invariant, unused.
    float* out = (float*)d_out;

    const int smem_bytes = (128 * 128 + 128 * 65) * (int)sizeof(float);  // ~96.5 KB
    cudaFuncSetAttribute(scores_kernel,
                         cudaFuncAttributeMaxDynamicSharedMemorySize, smem_bytes);

    scores_kernel<<<(BB * TT) / TM, 256, smem_bytes>>>(enc, W1w, W2w, W1b, W2b, Vw);
    ctx_kernel<<<BB, 512>>>(enc, out);
}

// round 4
// speedup vs baseline: 2.0040x; 2.0040x over previous
#include <cuda_runtime.h>
#include <cuda_bf16.h>
#include <math.h>
#include <stdint.h>

#define BB 64
#define TT 2048
#define DD 128
#define UU 128

#define WPAD 136                       // padded row length (elements) -> conflict-free frags

// ---------------- scratch (__device__ globals per allocation rules) --------
__device__ float g_scores[BB * TT];                 // 512 KB
__device__ float g_part[BB * 8 * DD];               // 256 KB
__device__ __nv_bfloat16 g_Whi[UU * WPAD];          // Wsum hi, [u][k] padded
__device__ __nv_bfloat16 g_Wlo[UU * WPAD];          // Wsum lo, [u][k] padded

// ---------------------------------------------------------------------------
// prep: Wsum = W1+W2 -> bf16 hi/lo stored [u][k] (B-operand layout, padded)
// ---------------------------------------------------------------------------
__global__ void prep_kernel(const float* __restrict__ W1, const float* __restrict__ W2) {
    int i = blockIdx.x * 256 + threadIdx.x;          // i = k*128 + u (W is [D][U] row-major)
    int k = i >> 7, u = i & 127;
    float w = W1[i] + W2[i];
    __nv_bfloat16 hi = __float2bfloat16_rn(w);
    __nv_bfloat16 lo = __float2bfloat16_rn(w - __bfloat162float(hi));
    g_Whi[u * WPAD + k] = hi;
    g_Wlo[u * WPAD + k] = lo;
}

// ---------------------------------------------------------------------------
// scores: per CTA 128 tokens. D[128x128] = X*Wsum via mma.sync m16n8k16 bf16
// (3-term split), then tanh + V-dot epilogue. grid=1024, 256 thr, ~138KB smem.
// Warp layout: wm = wid&3 -> rows wm*32..+31 ; wn = wid>>2 -> cols wn*64..+63
// ---------------------------------------------------------------------------
#define S_BIAS 0                       // float[128]
#define S_V    512                     // float[128]
#define S_PART 1024                    // float[2][128]
#define S_XHI  2048                    // bf16 [128][WPAD]
#define S_XLO  (S_XHI + 128 * WPAD * 2)
#define S_WHI  (S_XLO + 128 * WPAD * 2)
#define S_WLO  (S_WHI + 128 * WPAD * 2)
#define S_TOTAL (S_WLO + 128 * WPAD * 2)

__device__ __forceinline__ void mma16816(float* c, const uint32_t* a, const uint32_t* b) {
    asm volatile(
        "mma.sync.aligned.m16n8k16.row.col.f32.bf16.bf16.f32 "
        "{%0,%1,%2,%3}, {%4,%5,%6,%7}, {%8,%9}, {%0,%1,%2,%3};"
        : "+f"(c[0]), "+f"(c[1]), "+f"(c[2]), "+f"(c[3])
        : "r"(a[0]), "r"(a[1]), "r"(a[2]), "r"(a[3]), "r"(b[0]), "r"(b[1]));
}

__global__ void __launch_bounds__(256, 1) scores_mma(const float* __restrict__ x,
                                                     const float* __restrict__ b1,
                                                     const float* __restrict__ b2,
                                                     const float* __restrict__ Vw) {
    extern __shared__ __align__(16) char smem[];
    const int tid = threadIdx.x, wid = tid >> 5, lane = tid & 31;
    const int g = lane >> 2, q = lane & 3;           // frag groupID / threadID-in-group
    const int wm = wid & 3, wn = wid >> 2;

    if (tid < 128) {
        ((float*)(smem + S_BIAS))[tid] = b1[tid] + b2[tid];
        ((float*)(smem + S_V))[tid] = Vw[tid];
    }

    // Copy pre-split W [u][WPAD] hi/lo (L2-resident, uint4)
    {
        const uint4* whi = (const uint4*)g_Whi;
        const uint4* wlo = (const uint4*)g_Wlo;
        uint4* swhi = (uint4*)(smem + S_WHI);
        uint4* swlo = (uint4*)(smem + S_WLO);
#pragma unroll
        for (int i = tid; i < UU * WPAD / 8; i += 256) { swhi[i] = whi[i]; swlo[i] = wlo[i]; }
    }

    // Load + split X tile -> [token][WPAD] bf16 hi/lo
    {
        const float4* xt = (const float4*)(x + (size_t)blockIdx.x * 128 * 128);
#pragma unroll
        for (int i4 = tid; i4 < 4096; i4 += 256) {
            int r = i4 >> 5;             // token row
            int c = (i4 & 31) << 2;      // k col, multiple of 4
            float4 v = xt[i4];
            __nv_bfloat162 h0 = __float22bfloat162_rn(make_float2(v.x, v.y));
            __nv_bfloat162 h1 = __float22bfloat162_rn(make_float2(v.z, v.w));
            float2 ra = make_float2(v.x - __bfloat162float(h0.x), v.y - __bfloat162float(h0.y));
            float2 rb = make_float2(v.z - __bfloat162float(h1.x), v.w - __bfloat162float(h1.y));
            __nv_bfloat162 l0 = __float22bfloat162_rn(ra);
            __nv_bfloat162 l1 = __float22bfloat162_rn(rb);
            size_t off = ((size_t)r * WPAD + c) * 2;
            uint2 hv, lv;
            hv.x = *(uint32_t*)&h0; hv.y = *(uint32_t*)&h1;
            lv.x = *(uint32_t*)&l0; lv.y = *(uint32_t*)&l1;
            *(uint2*)(smem + S_XHI + off) = hv;
            *(uint2*)(smem + S_XLO + off) = lv;
        }
    }
    __syncthreads();

    float acc[2][8][4];
#pragma unroll
    for (int t = 0; t < 2; t++)
#pragma unroll
        for (int j = 0; j < 8; j++)
#pragma unroll
            for (int e = 0; e < 4; e++) acc[t][j][e] = 0.f;

    // 3 terms: Xhi*Whi, Xhi*Wlo, Xlo*Whi
#pragma unroll
    for (int term = 0; term < 3; term++) {
        const char* A = smem + (term == 2 ? S_XLO : S_XHI);
        const char* Bm = smem + (term == 1 ? S_WLO : S_WHI);
#pragma unroll
        for (int ks = 0; ks < 8; ks++) {
            const int k0 = ks * 16;
            uint32_t a[2][4];
#pragma unroll
            for (int t = 0; t < 2; t++) {
                const char* ab = A + (((wm * 32 + t * 16 + g) * WPAD) + k0 + 2 * q) * 2;
                a[t][0] = *(const uint32_t*)(ab);
                a[t][1] = *(const uint32_t*)(ab + 8 * WPAD * 2);
                a[t][2] = *(const uint32_t*)(ab + 16);
                a[t][3] = *(const uint32_t*)(ab + 8 * WPAD * 2 + 16);
            }
#pragma unroll
            for (int j = 0; j < 8; j++) {
                const char* bb = Bm + (((wn * 64 + j * 8 + g) * WPAD) + k0 + 2 * q) * 2;
                uint32_t b[2];
                b[0] = *(const uint32_t*)(bb);
                b[1] = *(const uint32_t*)(bb + 16);
                mma16816(acc[0][j], a[0], b);
                mma16816(acc[1][j], a[1], b);
            }
        }
    }

    // Epilogue: tanh + V-dot, reduce over u
    const float* sBias = (const float*)(smem + S_BIAS);
    const float* sV = (const float*)(smem + S_V);
    float p[4] = {0.f, 0.f, 0.f, 0.f};   // rows wm*32+g, +8, +16, +24
#pragma unroll
    for (int t = 0; t < 2; t++) {
#pragma unroll
        for (int j = 0; j < 8; j++) {
            const int u0 = wn * 64 + j * 8 + 2 * q;
            const float bia0 = sBias[u0], bia1 = sBias[u0 + 1];
            const float v0 = sV[u0], v1 = sV[u0 + 1];
            p[t * 2 + 0] += tanhf(acc[t][j][0] + bia0) * v0 + tanhf(acc[t][j][1] + bia1) * v1;
            p[t * 2 + 1] += tanhf(acc[t][j][2] + bia0) * v0 + tanhf(acc[t][j][3] + bia1) * v1;
        }
    }
    // reduce across the 4 lanes sharing the same rows (lane%4 = q)
#pragma unroll
    for (int e = 0; e < 4; e++) {
        p[e] += __shfl_xor_sync(~0u, p[e], 1);
        p[e] += __shfl_xor_sync(~0u, p[e], 2);
    }
    if (q == 0) {
        float* part = (float*)(smem + S_PART);
        part[wn * 128 + wm * 32 + g]      = p[0];
        part[wn * 128 + wm * 32 + g + 8]  = p[1];
        part[wn * 128 + wm * 32 + g + 16] = p[2];
        part[wn * 128 + wm * 32 + g + 24] = p[3];
    }
    __syncthreads();
    if (tid < 128) {
        const float* part = (const float*)(smem + S_PART);
        g_scores[(size_t)blockIdx.x * 128 + tid] = part[tid] + part[128 + tid];
    }
}

// ---------------------------------------------------------------------------
// ctx partial: grid = 64 batches x 8 slices, 256 threads.
// ---------------------------------------------------------------------------
__global__ void ctx_partial(const float* __restrict__ x) {
    __shared__ float attn[256];
    __shared__ float red[8];
    __shared__ float part[2][DD];
    const int b = blockIdx.x >> 3, s = blockIdx.x & 7, tid = threadIdx.x;
    const float* sc = g_scores + (size_t)b * TT;

    float m = -1e30f;
#pragma unroll
    for (int i = tid; i < TT; i += 256) m = fmaxf(m, sc[i]);
#pragma unroll
    for (int off = 16; off > 0; off >>= 1) m = fmaxf(m, __shfl_xor_sync(~0u, m, off));
    if ((tid & 31) == 0) red[tid >> 5] = m;
    __syncthreads();
    if (tid < 32) {
        float v = (tid < 8) ? red[tid] : -1e30f;
#pragma unroll
        for (int off = 4; off > 0; off >>= 1) v = fmaxf(v, __shfl_xor_sync(~0u, v, off));
        if (tid == 0) red[0] = v;
    }
    __syncthreads();
    m = red[0];
    __syncthreads();

    float sm = 0.f;
#pragma unroll
    for (int i = tid; i < TT; i += 256) sm += expf(sc[i] - m);
#pragma unroll
    for (int off = 16; off > 0; off >>= 1) sm += __shfl_xor_sync(~0u, sm, off);
    if ((tid & 31) == 0) red[tid >> 5] = sm;
    __syncthreads();
    if (tid < 32) {
        float v = (tid < 8) ? red[tid] : 0.f;
#pragma unroll
        for (int off = 4; off > 0; off >>= 1) v += __shfl_xor_sync(~0u, v, off);
        if (tid == 0) red[0] = v;
    }
    __syncthreads();
    const float inv = 1.f / red[0];

    attn[tid] = expf(sc[s * 256 + tid] - m) * inv;
    __syncthreads();

    const int gg = tid >> 7, d = tid & 127;
    const float* xb = x + ((size_t)b * TT + s * 256) * DD + d;
    float acc = 0.f;
#pragma unroll 8
    for (int t = gg; t < 256; t += 2) acc += attn[t] * xb[(size_t)t * DD];
    part[gg][d] = acc;
    __syncthreads();
    if (tid < DD)
        g_part[((size_t)b * 8 + s) * DD + tid] = part[0][tid] + part[1][tid];
}

__global__ void ctx_reduce(float* __restrict__ out) {
    const int b = blockIdx.x, d = threadIdx.x;
    float a = 0.f;
#pragma unroll
    for (int s = 0; s < 8; s++) a += g_part[((size_t)b * 8 + s) * DD + d];
    out[(size_t)b * DD + d] = a;
}

// ---------------------------------------------------------------------------
extern "C" void kernel_launch(void* const* d_in, const int* in_sizes, int n_in,
                              void* d_out, int out_size) {
    const float* enc = (const float*)d_in[0];
    const float* W1w = (const float*)d_in[1];
    const float* W1b = (const float*)d_in[2];
    const float* W2w = (const float*)d_in[3];
    const float* W2b = (const float*)d_in[4];
    const float* Vw  = (const float*)d_in[5];
    // d_in[6] = V_b: softmax-invariant.
    float* out = (float*)d_out;

    cudaFuncSetAttribute(scores_mma, cudaFuncAttributeMaxDynamicSharedMemorySize, S_TOTAL);

    prep_kernel<<<64, 256>>>(W1w, W2w);
    scores_mma<<<(BB * TT) / 128, 256, S_TOTAL>>>(enc, W1b, W2b, Vw);
    ctx_partial<<<BB * 8, 256>>>(enc);
    ctx_reduce<<<BB, 128>>>(out);
}

// round 5
// speedup vs baseline: 2.0545x; 1.0252x over previous
#include <cuda_runtime.h>
#include <cuda_bf16.h>
#include <math.h>
#include <stdint.h>

#define BB 64
#define TT 2048
#define DD 128
#define UU 128
#define WPAD 136                       // padded row length -> conflict-free frags
#define NTILE 16                       // tiles per batch (2048/128)
#define TSTRIDE 132                    // per-tile output stride: 128 c + m + s + pad

// ---------------- scratch (__device__ globals per allocation rules) --------
__device__ float g_tile[BB * NTILE * TSTRIDE];      // per-tile context partials
__device__ __nv_bfloat16 g_Whi[UU * WPAD];          // Wsum hi, [u][k] padded
__device__ __nv_bfloat16 g_Wlo[UU * WPAD];          // Wsum lo, [u][k] padded

// ---------------------------------------------------------------------------
// prep: Wsum = W1+W2 -> bf16 hi/lo stored [u][k] (B-operand layout, padded)
// ---------------------------------------------------------------------------
__global__ void prep_kernel(const float* __restrict__ W1, const float* __restrict__ W2) {
    int i = blockIdx.x * 256 + threadIdx.x;          // i = k*128 + u (W is [D][U])
    int k = i >> 7, u = i & 127;
    float w = W1[i] + W2[i];
    __nv_bfloat16 hi = __float2bfloat16_rn(w);
    __nv_bfloat16 lo = __float2bfloat16_rn(w - __bfloat162float(hi));
    g_Whi[u * WPAD + k] = hi;
    g_Wlo[u * WPAD + k] = lo;
}

// ---------------------------------------------------------------------------
// scores+ctx fused: per CTA 128 tokens of one batch.
//   H = X*Wsum (mma.sync bf16 3-term split) ; sc = V . tanh(H + bias)
//   tile-softmax: m, s = sum(exp), c[d] = sum(exp * x[t,d])   (x from smem hi+lo)
// grid = 1024, 256 threads, ~141KB dynamic smem, 1 CTA/SM.
// ---------------------------------------------------------------------------
#define S_BIAS 0
#define S_V    512
#define S_PART 1024                    // float[2][128]
#define S_SC   2048                    // float[128] tile scores -> attn weights
#define S_RED  2560                    // float[8]
#define S_CTX  2624                    // float[4][128] ctx partials
#define S_XHI  4864
#define S_XLO  (S_XHI + 128 * WPAD * 2)
#define S_WHI  (S_XLO + 128 * WPAD * 2)
#define S_WLO  (S_WHI + 128 * WPAD * 2)
#define S_TOTAL (S_WLO + 128 * WPAD * 2)

__device__ __forceinline__ void mma16816(float* c, const uint32_t* a, const uint32_t* b) {
    asm volatile(
        "mma.sync.aligned.m16n8k16.row.col.f32.bf16.bf16.f32 "
        "{%0,%1,%2,%3}, {%4,%5,%6,%7}, {%8,%9}, {%0,%1,%2,%3};"
        : "+f"(c[0]), "+f"(c[1]), "+f"(c[2]), "+f"(c[3])
        : "r"(a[0]), "r"(a[1]), "r"(a[2]), "r"(a[3]), "r"(b[0]), "r"(b[1]));
}

__global__ void __launch_bounds__(256, 1) scores_fused(const float* __restrict__ x,
                                                       const float* __restrict__ b1,
                                                       const float* __restrict__ b2,
                                                       const float* __restrict__ Vw) {
    extern __shared__ __align__(16) char smem[];
    const int tid = threadIdx.x, wid = tid >> 5, lane = tid & 31;
    const int g = lane >> 2, q = lane & 3;
    const int wm = wid & 3, wn = wid >> 2;

    if (tid < 128) {
        ((float*)(smem + S_BIAS))[tid] = b1[tid] + b2[tid];
        ((float*)(smem + S_V))[tid] = Vw[tid];
    }

    // W tiles (L2-resident after prep)
    {
        const uint4* whi = (const uint4*)g_Whi;
        const uint4* wlo = (const uint4*)g_Wlo;
        uint4* swhi = (uint4*)(smem + S_WHI);
        uint4* swlo = (uint4*)(smem + S_WLO);
#pragma unroll
        for (int i = tid; i < UU * WPAD / 8; i += 256) { swhi[i] = whi[i]; swlo[i] = wlo[i]; }
    }

    // Load + split X tile -> [token][WPAD] bf16 hi/lo
    {
        const float4* xt = (const float4*)(x + (size_t)blockIdx.x * 128 * 128);
#pragma unroll
        for (int i4 = tid; i4 < 4096; i4 += 256) {
            int r = i4 >> 5;
            int c = (i4 & 31) << 2;
            float4 v = xt[i4];
            __nv_bfloat162 h0 = __float22bfloat162_rn(make_float2(v.x, v.y));
            __nv_bfloat162 h1 = __float22bfloat162_rn(make_float2(v.z, v.w));
            float2 ra = make_float2(v.x - __bfloat162float(h0.x), v.y - __bfloat162float(h0.y));
            float2 rb = make_float2(v.z - __bfloat162float(h1.x), v.w - __bfloat162float(h1.y));
            __nv_bfloat162 l0 = __float22bfloat162_rn(ra);
            __nv_bfloat162 l1 = __float22bfloat162_rn(rb);
            size_t off = ((size_t)r * WPAD + c) * 2;
            uint2 hv, lv;
            hv.x = *(uint32_t*)&h0; hv.y = *(uint32_t*)&h1;
            lv.x = *(uint32_t*)&l0; lv.y = *(uint32_t*)&l1;
            *(uint2*)(smem + S_XHI + off) = hv;
            *(uint2*)(smem + S_XLO + off) = lv;
        }
    }
    __syncthreads();

    float acc[2][8][4];
#pragma unroll
    for (int t = 0; t < 2; t++)
#pragma unroll
        for (int j = 0; j < 8; j++)
#pragma unroll
            for (int e = 0; e < 4; e++) acc[t][j][e] = 0.f;

    // Mainloop: each distinct fragment loaded once; 3 split-terms from regs.
#pragma unroll
    for (int ks = 0; ks < 8; ks++) {
        const int k0 = ks * 16;
        uint32_t ah[2][4], al[2][4];
#pragma unroll
        for (int t = 0; t < 2; t++) {
            const int roff = ((wm * 32 + t * 16 + g) * WPAD + k0 + 2 * q) * 2;
            const char* ph = smem + S_XHI + roff;
            const char* pl = smem + S_XLO + roff;
            ah[t][0] = *(const uint32_t*)(ph);
            ah[t][1] = *(const uint32_t*)(ph + 8 * WPAD * 2);
            ah[t][2] = *(const uint32_t*)(ph + 16);
            ah[t][3] = *(const uint32_t*)(ph + 8 * WPAD * 2 + 16);
            al[t][0] = *(const uint32_t*)(pl);
            al[t][1] = *(const uint32_t*)(pl + 8 * WPAD * 2);
            al[t][2] = *(const uint32_t*)(pl + 16);
            al[t][3] = *(const uint32_t*)(pl + 8 * WPAD * 2 + 16);
        }
#pragma unroll
        for (int j = 0; j < 8; j++) {
            const int boff = ((wn * 64 + j * 8 + g) * WPAD + k0 + 2 * q) * 2;
            uint32_t bh[2], bl[2];
            bh[0] = *(const uint32_t*)(smem + S_WHI + boff);
            bh[1] = *(const uint32_t*)(smem + S_WHI + boff + 16);
            bl[0] = *(const uint32_t*)(smem + S_WLO + boff);
            bl[1] = *(const uint32_t*)(smem + S_WLO + boff + 16);
            mma16816(acc[0][j], ah[0], bh);
            mma16816(acc[1][j], ah[1], bh);
            mma16816(acc[0][j], ah[0], bl);
            mma16816(acc[1][j], ah[1], bl);
            mma16816(acc[0][j], al[0], bh);
            mma16816(acc[1][j], al[1], bh);
        }
    }

    // Epilogue: tanh + V-dot, reduce over u -> tile scores sc[128]
    const float* sBias = (const float*)(smem + S_BIAS);
    const float* sV = (const float*)(smem + S_V);
    float p[4] = {0.f, 0.f, 0.f, 0.f};
#pragma unroll
    for (int t = 0; t < 2; t++) {
#pragma unroll
        for (int j = 0; j < 8; j++) {
            const int u0 = wn * 64 + j * 8 + 2 * q;
            const float bia0 = sBias[u0], bia1 = sBias[u0 + 1];
            const float v0 = sV[u0], v1 = sV[u0 + 1];
            p[t * 2 + 0] += tanhf(acc[t][j][0] + bia0) * v0 + tanhf(acc[t][j][1] + bia1) * v1;
            p[t * 2 + 1] += tanhf(acc[t][j][2] + bia0) * v0 + tanhf(acc[t][j][3] + bia1) * v1;
        }
    }
#pragma unroll
    for (int e = 0; e < 4; e++) {
        p[e] += __shfl_xor_sync(~0u, p[e], 1);
        p[e] += __shfl_xor_sync(~0u, p[e], 2);
    }
    if (q == 0) {
        float* part = (float*)(smem + S_PART);
        part[wn * 128 + wm * 32 + g]      = p[0];
        part[wn * 128 + wm * 32 + g + 8]  = p[1];
        part[wn * 128 + wm * 32 + g + 16] = p[2];
        part[wn * 128 + wm * 32 + g + 24] = p[3];
    }
    __syncthreads();
    float* sc = (float*)(smem + S_SC);
    if (tid < 128) {
        const float* part = (const float*)(smem + S_PART);
        sc[tid] = part[tid] + part[128 + tid];
    }
    __syncthreads();

    // ---- tile softmax stats ----
    float* red = (float*)(smem + S_RED);
    {
        float v = sc[tid & 127];
#pragma unroll
        for (int off = 16; off > 0; off >>= 1) v = fmaxf(v, __shfl_xor_sync(~0u, v, off));
        if (lane == 0) red[wid] = v;
    }
    __syncthreads();
    float M = fmaxf(fmaxf(red[0], red[1]), fmaxf(red[2], red[3]));
    M = fmaxf(M, fmaxf(fmaxf(red[4], red[5]), fmaxf(red[6], red[7])));
    __syncthreads();
    // exp (threads <128 write attn back into sc), warp-sum partials
    float e_val = 0.f;
    if (tid < 128) {
        e_val = expf(sc[tid] - M);
    }
    {
        float v = e_val;
#pragma unroll
        for (int off = 16; off > 0; off >>= 1) v += __shfl_xor_sync(~0u, v, off);
        if (lane == 0) red[wid] = v;   // warps 4-7 contribute 0
    }
    if (tid < 128) sc[tid] = e_val;    // safe: sc re-read only after next sync
    __syncthreads();
    const float S = red[0] + red[1] + red[2] + red[3];

    // ---- tile context: c[d] = sum_t attn[t] * x[t][d] (x = hi+lo from smem) ----
    {
        const int h = tid >> 6;          // token group (32 tokens), 2 warps each
        const int pp = tid & 63;         // d-pair index -> d = 2pp, 2pp+1
        float2 cacc = make_float2(0.f, 0.f);
#pragma unroll 8
        for (int i = 0; i < 32; i++) {
            const int t = h * 32 + i;
            const float a = sc[t];       // broadcast
            const int off = (t * WPAD + 2 * pp) * 2;
            __nv_bfloat162 xh = *(const __nv_bfloat162*)(smem + S_XHI + off);
            __nv_bfloat162 xl = *(const __nv_bfloat162*)(smem + S_XLO + off);
            float2 fh = __bfloat1622float2(xh);
            float2 fl = __bfloat1622float2(xl);
            cacc.x = fmaf(a, fh.x + fl.x, cacc.x);
            cacc.y = fmaf(a, fh.y + fl.y, cacc.y);
        }
        ((float2*)(smem + S_CTX))[h * 64 + pp] = cacc;
    }
    __syncthreads();
    float* gout = g_tile + (size_t)blockIdx.x * TSTRIDE;
    if (tid < 128) {
        const float* cp = (const float*)(smem + S_CTX);
        gout[tid] = cp[tid] + cp[128 + tid] + cp[256 + tid] + cp[384 + tid];
    }
    if (tid == 128) gout[128] = M;
    if (tid == 129) gout[129] = S;
}

// ---------------------------------------------------------------------------
// combine: merge 16 tile-partials per batch with max-rescaling.
// grid = 64, 128 threads.
// ---------------------------------------------------------------------------
__global__ void combine_kernel(float* __restrict__ out) {
    const int b = blockIdx.x, d = threadIdx.x;
    const float* tb = g_tile + (size_t)b * NTILE * TSTRIDE;
    float M = -1e30f;
#pragma unroll
    for (int s = 0; s < NTILE; s++) M = fmaxf(M, tb[s * TSTRIDE + 128]);
    float S = 0.f, c = 0.f;
#pragma unroll
    for (int s = 0; s < NTILE; s++) {
        const float w = expf(tb[s * TSTRIDE + 128] - M);
        S = fmaf(tb[s * TSTRIDE + 129], w, S);
        c = fmaf(tb[s * TSTRIDE + d], w, c);
    }
    out[(size_t)b * DD + d] = c / S;
}

// ---------------------------------------------------------------------------
extern "C" void kernel_launch(void* const* d_in, const int* in_sizes, int n_in,
                              void* d_out, int out_size) {
    const float* enc = (const float*)d_in[0];
    const float* W1w = (const float*)d_in[1];
    const float* W1b = (const float*)d_in[2];
    const float* W2w = (const float*)d_in[3];
    const float* W2b = (const float*)d_in[4];
    const float* Vw  = (const float*)d_in[5];
    // d_in[6] = V_b: softmax-invariant.
    float* out = (float*)d_out;

    cudaFuncSetAttribute(scores_fused, cudaFuncAttributeMaxDynamicSharedMemorySize, S_TOTAL);

    prep_kernel<<<64, 256>>>(W1w, W2w);
    scores_fused<<<(BB * TT) / 128, 256, S_TOTAL>>>(enc, W1b, W2b, Vw);
    combine_kernel<<<BB, 128>>>(out);
}

// round 6
// speedup vs baseline: 2.3358x; 1.1369x over previous
#include <cuda_runtime.h>
#include <cuda_bf16.h>
#include <math.h>
#include <stdint.h>

#define BB 64
#define TT 2048
#define DD 128
#define UU 128
#define WPAD 136                        // padded row length -> conflict-free frags
#define NTILE 16                        // tiles per batch
#define NT (BB * NTILE)                 // 1024 tiles total
#define GRID 148                        // persistent CTAs
#define TSTRIDE 132                     // per-tile out: 128 ctx + m + s + pad

// ---------------- scratch ---------------------------------------------------
__device__ float g_tile[NT * TSTRIDE];

// ---------------- smem layout (bytes) ---------------------------------------
#define S_BIAS 0                        // float[128]
#define S_V    512                      // float[128]
#define S_PART 1024                     // float[2][128]
#define S_SC   2048                     // float[128]
#define S_RED  2560                     // float[8]
#define S_CTX  2624                     // float[4][128]
#define S_RAW  4736                     // float[128][128] raw x tile / W staging
#define S_XHI  (S_RAW + 65536)          // bf16[128][WPAD]
#define S_XLO  (S_XHI + 34816)
#define S_WHI  (S_XLO + 34816)
#define S_WLO  (S_WHI + 34816)
#define S_TOTAL (S_WLO + 34816)         // 209536 B = 204.6 KB

__device__ __forceinline__ uint32_t smem_u32(const void* p) {
    uint32_t a;
    asm("{ .reg .u64 t; cvta.to.shared.u64 t, %1; cvt.u32.u64 %0, t; }" : "=r"(a) : "l"(p));
    return a;
}
#define CP_ASYNC16(dst, src) \
    asm volatile("cp.async.cg.shared.global [%0], [%1], 16;" :: "r"(dst), "l"(src) : "memory")
#define CP_COMMIT() asm volatile("cp.async.commit_group;" ::: "memory")
#define CP_WAIT0()  asm volatile("cp.async.wait_group 0;" ::: "memory")

__device__ __forceinline__ void mma16816(float* c, const uint32_t* a, const uint32_t* b) {
    asm volatile(
        "mma.sync.aligned.m16n8k16.row.col.f32.bf16.bf16.f32 "
        "{%0,%1,%2,%3}, {%4,%5,%6,%7}, {%8,%9}, {%0,%1,%2,%3};"
        : "+f"(c[0]), "+f"(c[1]), "+f"(c[2]), "+f"(c[3])
        : "r"(a[0]), "r"(a[1]), "r"(a[2]), "r"(a[3]), "r"(b[0]), "r"(b[1]));
}

__device__ __forceinline__ float fast_tanh(float x) {
    x = fminf(fmaxf(x, -15.f), 15.f);
    float t = __expf(2.f * x);
    return 1.f - __fdividef(2.f, t + 1.f);
}

// ---------------------------------------------------------------------------
// persistent fused kernel: W prep once, then grid-stride over 1024 tiles with
// cp.async double-use of the raw buffer (fetch i+1 during compute of i).
// ---------------------------------------------------------------------------
__global__ void __launch_bounds__(256, 1) fused_kernel(const float* __restrict__ x,
                                                       const float* __restrict__ W1,
                                                       const float* __restrict__ W2,
                                                       const float* __restrict__ b1,
                                                       const float* __restrict__ b2,
                                                       const float* __restrict__ Vw) {
    extern __shared__ __align__(16) char smem[];
    const uint32_t raw_u32 = smem_u32(smem + S_RAW);
    const int tid = threadIdx.x, wid = tid >> 5, lane = tid & 31;
    const int g = lane >> 2, q = lane & 3;
    const int wm = wid & 3, wn = wid >> 2;
    float* rawf = (float*)(smem + S_RAW);

    // ---- one-time: bias/V + Wsum staged into raw, then transpose-split ----
    if (tid < 128) {
        ((float*)(smem + S_BIAS))[tid] = b1[tid] + b2[tid];
        ((float*)(smem + S_V))[tid] = Vw[tid];
    }
    {
        const float4* w1 = (const float4*)W1;
        const float4* w2 = (const float4*)W2;
        float4* r4 = (float4*)rawf;
#pragma unroll
        for (int i = tid; i < 4096; i += 256) {
            float4 a = w1[i], b = w2[i];
            float4 c;
            c.x = a.x + b.x; c.y = a.y + b.y; c.z = a.z + b.z; c.w = a.w + b.w;
            r4[i] = c;
        }
    }
    __syncthreads();
    {
        // thread t<128: u=t, k 0..63 ; t>=128: u=t-128, k 64..127
        const int u = tid & 127;
        const int k0 = (tid >> 7) * 64;
#pragma unroll
        for (int k = k0; k < k0 + 64; k += 2) {
            float w0 = rawf[k * 128 + u];
            float w1v = rawf[(k + 1) * 128 + u];
            __nv_bfloat16 h0 = __float2bfloat16_rn(w0);
            __nv_bfloat16 h1 = __float2bfloat16_rn(w1v);
            __nv_bfloat162 hp; hp.x = h0; hp.y = h1;
            __nv_bfloat162 lp;
            lp.x = __float2bfloat16_rn(w0 - __bfloat162float(h0));
            lp.y = __float2bfloat16_rn(w1v - __bfloat162float(h1));
            *(uint32_t*)(smem + S_WHI + (u * WPAD + k) * 2) = *(uint32_t*)&hp;
            *(uint32_t*)(smem + S_WLO + (u * WPAD + k) * 2) = *(uint32_t*)&lp;
        }
    }
    __syncthreads();

    // ---- prologue: fetch first tile ----
    int tile = blockIdx.x;
    if (tile < NT) {
        const char* src = (const char*)(x + (size_t)tile * 16384) + tid * 16;
#pragma unroll
        for (int n = 0; n < 16; n++)
            CP_ASYNC16(raw_u32 + tid * 16 + n * 4096, src + n * 4096);
        CP_COMMIT();
    }

    for (; tile < NT; tile += GRID) {
        CP_WAIT0();
        __syncthreads();

        // ---- convert raw fp32 -> bf16 hi/lo ----
#pragma unroll
        for (int i4 = tid; i4 < 4096; i4 += 256) {
            int r = i4 >> 5;
            int c = (i4 & 31) << 2;
            float4 v = ((const float4*)rawf)[i4];
            __nv_bfloat162 h0 = __float22bfloat162_rn(make_float2(v.x, v.y));
            __nv_bfloat162 h1 = __float22bfloat162_rn(make_float2(v.z, v.w));
            float2 ra = make_float2(v.x - __bfloat162float(h0.x), v.y - __bfloat162float(h0.y));
            float2 rb = make_float2(v.z - __bfloat162float(h1.x), v.w - __bfloat162float(h1.y));
            __nv_bfloat162 l0 = __float22bfloat162_rn(ra);
            __nv_bfloat162 l1 = __float22bfloat162_rn(rb);
            size_t off = ((size_t)r * WPAD + c) * 2;
            uint2 hv, lv;
            hv.x = *(uint32_t*)&h0; hv.y = *(uint32_t*)&h1;
            lv.x = *(uint32_t*)&l0; lv.y = *(uint32_t*)&l1;
            *(uint2*)(smem + S_XHI + off) = hv;
            *(uint2*)(smem + S_XLO + off) = lv;
        }
        __syncthreads();

        // ---- prefetch next tile into raw (overlaps mainloop+epilogue) ----
        {
            const int next = tile + GRID;
            if (next < NT) {
                const char* src = (const char*)(x + (size_t)next * 16384) + tid * 16;
#pragma unroll
                for (int n = 0; n < 16; n++)
                    CP_ASYNC16(raw_u32 + tid * 16 + n * 4096, src + n * 4096);
                CP_COMMIT();
            }
        }

        // ---- mainloop: 3-term bf16 split MMA ----
        float acc[2][8][4];
#pragma unroll
        for (int t = 0; t < 2; t++)
#pragma unroll
            for (int j = 0; j < 8; j++)
#pragma unroll
                for (int e = 0; e < 4; e++) acc[t][j][e] = 0.f;

#pragma unroll
        for (int ks = 0; ks < 8; ks++) {
            const int k0 = ks * 16;
            uint32_t ah[2][4], al[2][4];
#pragma unroll
            for (int t = 0; t < 2; t++) {
                const int roff = ((wm * 32 + t * 16 + g) * WPAD + k0 + 2 * q) * 2;
                const char* ph = smem + S_XHI + roff;
                const char* pl = smem + S_XLO + roff;
                ah[t][0] = *(const uint32_t*)(ph);
                ah[t][1] = *(const uint32_t*)(ph + 8 * WPAD * 2);
                ah[t][2] = *(const uint32_t*)(ph + 16);
                ah[t][3] = *(const uint32_t*)(ph + 8 * WPAD * 2 + 16);
                al[t][0] = *(const uint32_t*)(pl);
                al[t][1] = *(const uint32_t*)(pl + 8 * WPAD * 2);
                al[t][2] = *(const uint32_t*)(pl + 16);
                al[t][3] = *(const uint32_t*)(pl + 8 * WPAD * 2 + 16);
            }
#pragma unroll
            for (int j = 0; j < 8; j++) {
                const int boff = ((wn * 64 + j * 8 + g) * WPAD + k0 + 2 * q) * 2;
                uint32_t bh[2], bl[2];
                bh[0] = *(const uint32_t*)(smem + S_WHI + boff);
                bh[1] = *(const uint32_t*)(smem + S_WHI + boff + 16);
                bl[0] = *(const uint32_t*)(smem + S_WLO + boff);
                bl[1] = *(const uint32_t*)(smem + S_WLO + boff + 16);
                mma16816(acc[0][j], ah[0], bh);
                mma16816(acc[1][j], ah[1], bh);
                mma16816(acc[0][j], ah[0], bl);
                mma16816(acc[1][j], ah[1], bl);
                mma16816(acc[0][j], al[0], bh);
                mma16816(acc[1][j], al[1], bh);
            }
        }

        // ---- epilogue: tanh + V-dot -> tile scores ----
        const float* sBias = (const float*)(smem + S_BIAS);
        const float* sV = (const float*)(smem + S_V);
        float p[4] = {0.f, 0.f, 0.f, 0.f};
#pragma unroll
        for (int t = 0; t < 2; t++) {
#pragma unroll
            for (int j = 0; j < 8; j++) {
                const int u0 = wn * 64 + j * 8 + 2 * q;
                const float bia0 = sBias[u0], bia1 = sBias[u0 + 1];
                const float v0 = sV[u0], v1 = sV[u0 + 1];
                p[t * 2 + 0] += fast_tanh(acc[t][j][0] + bia0) * v0
                              + fast_tanh(acc[t][j][1] + bia1) * v1;
                p[t * 2 + 1] += fast_tanh(acc[t][j][2] + bia0) * v0
                              + fast_tanh(acc[t][j][3] + bia1) * v1;
            }
        }
#pragma unroll
        for (int e = 0; e < 4; e++) {
            p[e] += __shfl_xor_sync(~0u, p[e], 1);
            p[e] += __shfl_xor_sync(~0u, p[e], 2);
        }
        if (q == 0) {
            float* part = (float*)(smem + S_PART);
            part[wn * 128 + wm * 32 + g]      = p[0];
            part[wn * 128 + wm * 32 + g + 8]  = p[1];
            part[wn * 128 + wm * 32 + g + 16] = p[2];
            part[wn * 128 + wm * 32 + g + 24] = p[3];
        }
        __syncthreads();
        float* sc = (float*)(smem + S_SC);
        if (tid < 128) {
            const float* part = (const float*)(smem + S_PART);
            sc[tid] = part[tid] + part[128 + tid];
        }
        __syncthreads();

        // ---- tile softmax stats ----
        float* red = (float*)(smem + S_RED);
        {
            float v = sc[tid & 127];
#pragma unroll
            for (int off = 16; off > 0; off >>= 1) v = fmaxf(v, __shfl_xor_sync(~0u, v, off));
            if (lane == 0) red[wid] = v;
        }
        __syncthreads();
        float M = fmaxf(fmaxf(red[0], red[1]), fmaxf(red[2], red[3]));
        M = fmaxf(M, fmaxf(fmaxf(red[4], red[5]), fmaxf(red[6], red[7])));
        __syncthreads();
        float e_val = 0.f;
        if (tid < 128) e_val = __expf(sc[tid] - M);
        {
            float v = e_val;
#pragma unroll
            for (int off = 16; off > 0; off >>= 1) v += __shfl_xor_sync(~0u, v, off);
            if (lane == 0) red[wid] = v;
        }
        if (tid < 128) sc[tid] = e_val;
        __syncthreads();
        const float S = red[0] + red[1] + red[2] + red[3];

        // ---- tile context from smem x (hi+lo) ----
        {
            const int h = tid >> 6;
            const int pp = tid & 63;
            float2 cacc = make_float2(0.f, 0.f);
#pragma unroll 8
            for (int i = 0; i < 32; i++) {
                const int t = h * 32 + i;
                const float a = sc[t];
                const int off = (t * WPAD + 2 * pp) * 2;
                __nv_bfloat162 xh = *(const __nv_bfloat162*)(smem + S_XHI + off);
                __nv_bfloat162 xl = *(const __nv_bfloat162*)(smem + S_XLO + off);
                float2 fh = __bfloat1622float2(xh);
                float2 fl = __bfloat1622float2(xl);
                cacc.x = fmaf(a, fh.x + fl.x, cacc.x);
                cacc.y = fmaf(a, fh.y + fl.y, cacc.y);
            }
            ((float2*)(smem + S_CTX))[h * 64 + pp] = cacc;
        }
        __syncthreads();
        float* gout = g_tile + (size_t)tile * TSTRIDE;
        if (tid < 128) {
            const float* cp = (const float*)(smem + S_CTX);
            gout[tid] = cp[tid] + cp[128 + tid] + cp[256 + tid] + cp[384 + tid];
        }
        if (tid == 128) gout[128] = M;
        if (tid == 129) gout[129] = S;
        __syncthreads();   // protect S_XHI/S_XLO/sc before next tile's convert
    }
}

// ---------------------------------------------------------------------------
// combine: merge 16 tile-partials per batch with max-rescaling. grid=64.
// ---------------------------------------------------------------------------
__global__ void combine_kernel(float* __restrict__ out) {
    const int b = blockIdx.x, d = threadIdx.x;
    const float* tb = g_tile + (size_t)b * NTILE * TSTRIDE;
    float M = -1e30f;
#pragma unroll
    for (int s = 0; s < NTILE; s++) M = fmaxf(M, tb[s * TSTRIDE + 128]);
    float S = 0.f, c = 0.f;
#pragma unroll
    for (int s = 0; s < NTILE; s++) {
        const float w = __expf(tb[s * TSTRIDE + 128] - M);
        S = fmaf(tb[s * TSTRIDE + 129], w, S);
        c = fmaf(tb[s * TSTRIDE + d], w, c);
    }
    out[(size_t)b * DD + d] = c / S;
}

// ---------------------------------------------------------------------------
extern "C" void kernel_launch(void* const* d_in, const int* in_sizes, int n_in,
                              void* d_out, int out_size) {
    const float* enc = (const float*)d_in[0];
    const float* W1w = (const float*)d_in[1];
    const float* W1b = (const float*)d_in[2];
    const float* W2w = (const float*)d_in[3];
    const float* W2b = (const float*)d_in[4];
    const float* Vw  = (const float*)d_in[5];
    // d_in[6] = V_b: softmax-invariant.
    float* out = (float*)d_out;

    cudaFuncSetAttribute(fused_kernel, cudaFuncAttributeMaxDynamicSharedMemorySize, S_TOTAL);

    fused_kernel<<<GRID, 256, S_TOTAL>>>(enc, W1w, W2w, W1b, W2b, Vw);
    combine_kernel<<<BB, 128>>>(out);
}